// round 4
// baseline (speedup 1.0000x reference)
#include <cuda_runtime.h>
#include <stdint.h>

// ---------------------------------------------------------------------------
// FasterRCNN RPN proposal head, round 4: TWO launches total.
//  Launch 1 (persistent, software grid barriers):
//    zero -> stream pass (hist>0.9 + spill) -> cutoff -> compact ->
//    rank+decode (fused) -> IoU mask matrix
//  Launch 2: NMS serial scan (1 block, 200KB smem staging).
// Exactness: softmax p1 bit-identical (single expf), top-k ordering on
// (score_bits desc, idx asc), fallback full-rescan path if cutoff < 0.9.
// ---------------------------------------------------------------------------

#define HF 512
#define WF 512
#define KA 9
#define NANCH (HF * WF * KA)       // 2359296
#define NANCH2 (NANCH / 2)
#define IMGW 16384.0f
#define IMGH 16384.0f
#define TOPK_N 4000
#define THR 0.5f
#define IOU_T 0.3f
#define NW 63
#define NBINS 65536
#define CAP 16384
#define BITS_BASE 0x3F000000u      // bits of 0.5f
#define SPILL_S 0.9f
#define PREF_MIN_BIN 52430u        // bin(bits(0.9f)) + safety
#define SPILLCAP 400000
#define RMAX 416                   // staged NMS rows (416*63*8 = 209664 B)

typedef unsigned long long ull;

// ---- scratch ---------------------------------------------------------------
__device__ uint32_t d_hist[NBINS];
__device__ uint32_t d_cutbin;
__device__ uint32_t d_count;
__device__ uint32_t d_spillcount;
__device__ int      d_fallback;
__device__ ull      d_spill[SPILLCAP];
__device__ ull      d_keys[CAP];
__device__ float d_bx1[TOPK_N], d_by1[TOPK_N], d_bx2[TOPK_N], d_by2[TOPK_N], d_ar[TOPK_N];
__device__ int   d_valid[TOPK_N];
__device__ ull   d_mask[TOPK_N * NW];
__device__ ull   d_rnz[NW];

// ---- software grid barrier (replay-safe: gen is monotone, count self-resets)
__device__ unsigned int          g_barcnt = 0;
__device__ volatile unsigned int g_bargen = 0;

__device__ __forceinline__ void gridbar() {
    __syncthreads();
    if (threadIdx.x == 0) {
        __threadfence();
        unsigned int g = g_bargen;               // read gen BEFORE arrival
        if (atomicAdd(&g_barcnt, 1u) == gridDim.x - 1) {
            g_barcnt = 0;
            __threadfence();
            g_bargen = g + 1;
        } else {
            while (g_bargen == g) __nanosleep(64);
        }
        __threadfence();
    }
    __syncthreads();
}

// p1 of 2-way softmax, bit-identical to jax.nn.softmax (max-side exp == 1.0f).
// Caller guarantees l1 > l0.
__device__ __forceinline__ float score_p1_pos(float l0, float l1) {
    float x = expf(l0 - l1);
    return 1.0f / (x + 1.0f);
}

__device__ __forceinline__ void cutoff_scan(int t) {
    // block 0, 256 threads. Smallest bin B with count(bins >= B) >= TOPK_N.
    __shared__ uint32_t csum[256], sfine[256];
    __shared__ int s_c;
    __shared__ uint32_t s_acc;
    int warp = t >> 5, lane = t & 31;
    for (int c = warp; c < 256; c += 8) {
        uint32_t s = 0;
        for (int b = lane; b < 256; b += 32) s += d_hist[c * 256 + b];
        #pragma unroll
        for (int o = 16; o; o >>= 1) s += __shfl_down_sync(0xFFFFFFFFu, s, o);
        if (lane == 0) csum[c] = s;
    }
    __syncthreads();
    if (t == 0) {
        uint32_t acc = 0; int c;
        for (c = 255; c >= 0; c--) {
            if (acc + csum[c] >= TOPK_N) break;
            acc += csum[c];
        }
        s_c = c; s_acc = acc;
    }
    __syncthreads();
    if (s_c >= 0) sfine[t] = d_hist[s_c * 256 + t];
    __syncthreads();
    if (t == 0) {
        uint32_t cut = 0;
        if (s_c >= 0) {
            uint32_t acc = s_acc; int b;
            for (b = 255; b >= 0; b--) {
                acc += sfine[b];
                if (acc >= TOPK_N) break;
            }
            if (b < 0) b = 0;
            cut = (uint32_t)(s_c * 256 + b);
        }
        d_cutbin = cut;
        int fb = 0;
        if (cut < PREF_MIN_BIN) fb = 1;
        if (d_spillcount > SPILLCAP) fb = 1;
        d_fallback = fb;
    }
}

__global__ void __launch_bounds__(256)
k_main(const float4* __restrict__ obj4,
       const float*  __restrict__ obj,
       const float*  __restrict__ reg,
       const float*  __restrict__ anch,
       float* __restrict__ out) {
    const int t   = threadIdx.x;
    const int tid = blockIdx.x * 256 + t;
    const int gsz = gridDim.x * 256;

    __shared__ ull s_stage[512];
    __shared__ uint32_t s_cnt, s_base;
    __shared__ ull s_tile[1024];
    __shared__ float s_cx1[4][64], s_cy1[4][64], s_cx2[4][64], s_cy2[4][64], s_ca[4][64];

    // ---------------- Phase Z: zero scratch + output boxes/scores ----------
    for (int i = tid; i < NBINS; i += gsz) d_hist[i] = 0u;
    for (int i = tid; i < 6 * TOPK_N; i += gsz) out[i] = 0.0f;
    for (int i = tid; i < TOPK_N; i += gsz) {
        d_valid[i] = 0;
        d_bx1[i] = 0.f; d_by1[i] = 0.f; d_bx2[i] = 0.f; d_by2[i] = 0.f; d_ar[i] = 0.f;
    }
    if (tid < NW) d_rnz[tid] = 0ull;
    if (tid == 0) { d_count = 0u; d_spillcount = 0u; d_cutbin = 0u; d_fallback = 0; }
    gridbar();

    // ---------------- Phase P1: stream obj, hist (s>0.9) + spill -----------
    {
        int iters = (NANCH2 + gsz - 1) / gsz;
        for (int it = 0; it < iters; it++) {
            __syncthreads();
            if (t == 0) s_cnt = 0u;
            __syncthreads();
            int i2 = tid + it * gsz;
            if (i2 < NANCH2) {
                float4 v = obj4[i2];
                #pragma unroll
                for (int h = 0; h < 2; h++) {
                    float l0 = h ? v.z : v.x;
                    float l1 = h ? v.w : v.y;
                    if (l1 > l0) {
                        float s = score_p1_pos(l0, l1);
                        if (s > SPILL_S) {
                            uint32_t sb = __float_as_uint(s);
                            uint32_t b  = (sb - BITS_BASE) >> 7;
                            if (b > (NBINS - 1)) b = NBINS - 1;
                            atomicAdd(&d_hist[b], 1u);
                            uint32_t p = atomicAdd(&s_cnt, 1u);
                            uint32_t idx = 2u * (uint32_t)i2 + (uint32_t)h;
                            s_stage[p] = ((ull)sb << 32) | (ull)(~idx);
                        }
                    }
                }
            }
            __syncthreads();
            if (t == 0 && s_cnt) s_base = atomicAdd(&d_spillcount, s_cnt);
            __syncthreads();
            for (int p = t; p < (int)s_cnt; p += 256) {
                uint32_t gp = s_base + p;
                if (gp < SPILLCAP) d_spill[gp] = s_stage[p];
            }
        }
    }
    gridbar();

    // ---------------- Phase C: cutoff (block 0) ----------------------------
    if (blockIdx.x == 0) cutoff_scan(t);
    gridbar();

    // ---------------- Phase CP: compact ------------------------------------
    int fb = d_fallback;
    if (!fb) {
        uint32_t cut = d_cutbin;
        uint32_t n = d_spillcount; if (n > SPILLCAP) n = SPILLCAP;
        for (uint32_t i = tid; i < n; i += gsz) {
            ull key = d_spill[i];
            uint32_t sb = (uint32_t)(key >> 32);
            uint32_t b  = (sb - BITS_BASE) >> 7;
            if (b > (NBINS - 1)) b = NBINS - 1;
            if (b >= cut) {
                uint32_t p = atomicAdd(&d_count, 1u);
                if (p < CAP) d_keys[p] = key;
            }
        }
        gridbar();
    } else {
        // complement histogram (s in (0.5, 0.9]) -> full hist
        for (int i2 = tid; i2 < NANCH2; i2 += gsz) {
            float4 v = obj4[i2];
            #pragma unroll
            for (int h = 0; h < 2; h++) {
                float l0 = h ? v.z : v.x;
                float l1 = h ? v.w : v.y;
                if (l1 > l0) {
                    float s = score_p1_pos(l0, l1);
                    if (s > THR && !(s > SPILL_S)) {
                        uint32_t sb = __float_as_uint(s);
                        uint32_t b  = (sb - BITS_BASE) >> 7;
                        if (b > (NBINS - 1)) b = NBINS - 1;
                        atomicAdd(&d_hist[b], 1u);
                    }
                }
            }
        }
        gridbar();
        if (blockIdx.x == 0) cutoff_scan(t);
        gridbar();
        uint32_t cut = d_cutbin;
        for (int i2 = tid; i2 < NANCH2; i2 += gsz) {
            float4 v = obj4[i2];
            #pragma unroll
            for (int h = 0; h < 2; h++) {
                float l0 = h ? v.z : v.x;
                float l1 = h ? v.w : v.y;
                if (l1 > l0) {
                    float s = score_p1_pos(l0, l1);
                    if (s > THR) {
                        uint32_t sb = __float_as_uint(s);
                        uint32_t b  = (sb - BITS_BASE) >> 7;
                        if (b > (NBINS - 1)) b = NBINS - 1;
                        if (b >= cut) {
                            uint32_t p = atomicAdd(&d_count, 1u);
                            uint32_t idx = 2u * (uint32_t)i2 + (uint32_t)h;
                            if (p < CAP) d_keys[p] = ((ull)sb << 32) | (ull)(~idx);
                        }
                    }
                }
            }
        }
        gridbar();
    }

    // ---------------- Phase R: rank + decode (fused) -----------------------
    {
        uint32_t cnt = d_count; if (cnt > CAP) cnt = CAP;
        int iters = (CAP + gsz - 1) / gsz;
        for (int it = 0; it < iters; it++) {
            int i = tid + it * gsz;
            int blockbase = blockIdx.x * 256 + it * gsz;
            if (blockbase >= (int)cnt) continue;   // whole block idle, uniform
            ull mykey = (i < (int)cnt) ? d_keys[i] : 0ull;
            int rank = 0;
            int ntiles = ((int)cnt + 1023) / 1024;
            for (int tb = 0; tb < ntiles; tb++) {
                for (int u = t; u < 1024; u += 256) {
                    int j = tb * 1024 + u;
                    s_tile[u] = (j < (int)cnt) ? d_keys[j] : 0ull;
                }
                __syncthreads();
                if (i < (int)cnt) {
                    int lim = (int)cnt - tb * 1024; if (lim > 1024) lim = 1024;
                    for (int u = 0; u < lim; u++) rank += (s_tile[u] > mykey) ? 1 : 0;
                }
                __syncthreads();
            }
            if (i < (int)cnt && rank < TOPK_N) {
                uint32_t idx = ~((uint32_t)mykey);
                float2 l = ((const float2*)obj)[idx];
                float p0, p1;
                if (l.y >= l.x) {
                    float x = expf(l.x - l.y);
                    float den = x + 1.0f;
                    p0 = x / den; p1 = 1.0f / den;
                } else {
                    float y = expf(l.y - l.x);
                    float den = 1.0f + y;
                    p0 = 1.0f / den; p1 = y / den;
                }
                float4 rg = ((const float4*)reg)[idx];
                float4 a  = ((const float4*)anch)[idx];
                float cx = (a.x + a.z * 0.5f) + rg.x * a.z;
                float cy = (a.y + a.w * 0.5f) + rg.y * a.w;
                float w  = a.z * expf(rg.z);
                float h  = a.w * expf(rg.w);
                float bx = cx - w * 0.5f;
                float by = cy - h * 0.5f;
                float x1 = fminf(fmaxf(bx, 0.f), IMGW);
                float y1 = fminf(fmaxf(by, 0.f), IMGH);
                float x2 = fminf(fmaxf(bx + w, 0.f), IMGW);
                float y2 = fminf(fmaxf(by + h, 0.f), IMGH);
                float bw = x2 - x1, bh = y2 - y1;
                out[rank * 4 + 0] = x1;
                out[rank * 4 + 1] = y1;
                out[rank * 4 + 2] = bw;
                out[rank * 4 + 3] = bh;
                out[4 * TOPK_N + rank * 2 + 0] = p0;
                out[4 * TOPK_N + rank * 2 + 1] = p1;
                d_bx1[rank] = x1;
                d_by1[rank] = y1;
                d_bx2[rank] = x1 + bw;
                d_by2[rank] = y1 + bh;
                d_ar[rank]  = bw * bh;
                d_valid[rank] = (p1 > THR) ? 1 : 0;
            }
        }
    }
    gridbar();

    // ---------------- Phase M: IoU mask matrix (all words written) ---------
    {
        const int sub  = t >> 6;       // 4 sub-tiles per block
        const int lane = t & 63;
        const int TT = NW * NW;        // 3969 tiles
        int iters = (TT + gridDim.x * 4 - 1) / (gridDim.x * 4);
        for (int it = 0; it < iters; it++) {
            int tile = (blockIdx.x + it * gridDim.x) * 4 + sub;
            int rb = 0, cb = 0;
            bool tv = tile < TT;
            if (tv) { rb = tile / NW; cb = tile - rb * NW; }
            bool comp = tv && (cb >= rb);
            if (comp) {
                int cj = cb * 64 + lane;
                if (cj < TOPK_N) {
                    s_cx1[sub][lane] = d_bx1[cj]; s_cy1[sub][lane] = d_by1[cj];
                    s_cx2[sub][lane] = d_bx2[cj]; s_cy2[sub][lane] = d_by2[cj];
                    s_ca[sub][lane]  = d_ar[cj];
                }
            }
            __syncthreads();
            if (tv) {
                int i = rb * 64 + lane;
                if (i < TOPK_N) {
                    ull wbits = 0ull;
                    if (comp) {
                        float x1 = d_bx1[i], y1 = d_by1[i];
                        float x2 = d_bx2[i], y2 = d_by2[i], ar = d_ar[i];
                        int jmax = TOPK_N - cb * 64; if (jmax > 64) jmax = 64;
                        for (int u = 0; u < jmax; u++) {
                            int j = cb * 64 + u;
                            if (j <= i) continue;
                            float iw = fmaxf(fminf(x2, s_cx2[sub][u]) - fmaxf(x1, s_cx1[sub][u]), 0.f);
                            float ih = fmaxf(fminf(y2, s_cy2[sub][u]) - fmaxf(y1, s_cy1[sub][u]), 0.f);
                            float inter = iw * ih;
                            float iou = inter / (ar + s_ca[sub][u] - inter + 1e-8f);
                            if (iou > IOU_T) wbits |= (1ull << u);
                        }
                    }
                    d_mask[(size_t)i * NW + cb] = wbits;
                    if (wbits) atomicOr(&d_rnz[i >> 6], 1ull << (i & 63));
                }
            }
            __syncthreads();
        }
    }
}

// ---------------- NMS: serial scan, register-resident state ----------------
__global__ void k_nms(float* __restrict__ out) {
    extern __shared__ ull s_mask[];   // RMAX * NW
    __shared__ ull s_rnz[NW], s_remv[NW], s_vb[NW];
    __shared__ int s_list[RMAX];
    __shared__ int s_wpref[NW];
    __shared__ int s_R;
    int t = threadIdx.x;  // 1024 threads

    if (t < NW) { s_rnz[t] = d_rnz[t]; s_vb[t] = 0ull; }
    __syncthreads();
    if (t == 0) {
        int acc = 0;
        for (int w = 0; w < NW; w++) { s_wpref[w] = acc; acc += __popcll(s_rnz[w]); }
        s_R = acc;
    }
    for (int i = t; i < TOPK_N; i += 1024)
        if (d_valid[i]) atomicOr(&s_vb[i >> 6], 1ull << (i & 63));
    __syncthreads();
    if (t < NW) {
        ull bits = s_rnz[t];
        int slot = s_wpref[t];
        while (bits) {
            int b = __ffsll((long long)bits) - 1;
            bits &= bits - 1ull;
            if (slot < RMAX) s_list[slot] = t * 64 + b;
            slot++;
        }
    }
    __syncthreads();
    int Rc = s_R < RMAX ? s_R : RMAX;
    for (int e = t; e < Rc * NW; e += 1024) {
        int slot = e / NW;
        int c    = e - slot * NW;
        s_mask[e] = d_mask[(size_t)s_list[slot] * NW + c];
    }
    __syncthreads();

    if (t < 32) {
        int l = t;
        ull r0 = 0ull, r1 = 0ull;
        for (int w = 0; w < NW; w++) {
            ull v0 = __shfl_sync(0xFFFFFFFFu, r0, w & 31);
            ull v1 = __shfl_sync(0xFFFFFFFFu, r1, w & 31);
            ull remw = (w < 32) ? v0 : v1;
            ull act = s_rnz[w] & s_vb[w] & ~remw;
            while (act) {
                int b = __ffsll((long long)act) - 1;
                act &= act - 1ull;
                int slot = s_wpref[w] + __popcll(s_rnz[w] & ((1ull << b) - 1ull));
                const ull* src = (slot < RMAX)
                    ? &s_mask[(size_t)slot * NW]
                    : &d_mask[(size_t)(w * 64 + b) * NW];
                r0 |= src[l];
                if (l + 32 < NW) r1 |= src[l + 32];
                act &= ~src[w];
            }
        }
        s_remv[l] = r0;
        if (l + 32 < NW) s_remv[l + 32] = r1;
    }
    __syncthreads();
    for (int i = t; i < TOPK_N; i += 1024) {
        bool kp = ((s_vb[i >> 6] >> (i & 63)) & 1ull) &&
                  !((s_remv[i >> 6] >> (i & 63)) & 1ull);
        out[6 * TOPK_N + i] = kp ? 1.0f : 0.0f;
    }
}

extern "C" void kernel_launch(void* const* d_in, const int* in_sizes, int n_in,
                              void* d_out, int out_size) {
    (void)in_sizes; (void)n_in; (void)out_size;
    const float* obj  = (const float*)d_in[0];
    const float* reg  = (const float*)d_in[1];
    const float* anch = (const float*)d_in[2];
    float* out = (float*)d_out;

    // grid sized for guaranteed co-residency (software barriers need it)
    int dev = 0, sms = 0, bpm = 0;
    cudaGetDevice(&dev);
    cudaDeviceGetAttribute(&sms, cudaDevAttrMultiProcessorCount, dev);
    cudaOccupancyMaxActiveBlocksPerMultiprocessor(&bpm, k_main, 256, 0);
    if (bpm < 1) bpm = 1;
    if (bpm > 8) bpm = 8;
    int grid = sms * bpm;
    if (grid < 1) grid = 1;

    const int NMS_SMEM = RMAX * NW * (int)sizeof(ull);  // 209664
    cudaFuncSetAttribute(k_nms, cudaFuncAttributeMaxDynamicSharedMemorySize, NMS_SMEM);

    k_main<<<grid, 256>>>((const float4*)obj, obj, reg, anch, out);
    k_nms <<<1, 1024, NMS_SMEM>>>(out);
}